// round 7
// baseline (speedup 1.0000x reference)
#include <cuda_runtime.h>
#include <math.h>
#include <stdint.h>

// ---------------------------------------------------------------------------
// CombinedElevationEncoder — both convs on bf16 m16n8k16 mma.sync.
//
// Insight 1: dual-CNN branch only consumed through (4,4) block-mean pool ->
//            fuse conv1+relu+conv2+relu+pool; activations never touch GMEM.
// Insight 2: spiking LSTM emits spike(mem-1), mem = sig(o)*tanh(syn) <= 1
//            -> all spikes exactly 0 -> sconv_res == b_proj; scan skipped.
// R7: R5 broadcast-LDS operands (cheap: fragment lanes overlap -> crossbar
//     broadcasts) + ILP to break dependent HMMA chains (conv1: 2 chunks/warp
//     interleaved; conv2: 4 chunks interleaved). Head: 768 blocks, 8-way
//     k-split (occupancy was the ceiling).
// ---------------------------------------------------------------------------

#define BATCH 32
#define HH    128
#define WW    1536
#define TH    16
#define TW    64
#define GX    (WW / TW)  // 24
#define GY    (HH / TH)  // 8
#define NCONTRIB 12

#define IN_ROWS 22
#define IN_STR  88       // input tile cols (bf16x2 words, ic-interleaved)
#define C1_STR  80       // conv1 plane cols (positions per row)

// partial pooled sums: [b][oc][ph][pw][contrib]
__device__ float g_partial[BATCH * 8 * 4 * 4 * NCONTRIB];

// pack two fp32 -> bf16x2 (lo = first arg)
__device__ __forceinline__ uint32_t bfpack(float lo, float hi) {
    uint32_t d;
    asm("cvt.rn.bf16x2.f32 %0, %1, %2;" : "=r"(d) : "f"(hi), "f"(lo));
    return d;
}

// m16n8k16 bf16 mma, accumulate in place (fp32 accum)
__device__ __forceinline__ void mma_bf16(float& c0, float& c1, float& c2, float& c3,
                                         uint32_t a0, uint32_t a1, uint32_t a2, uint32_t a3,
                                         uint32_t b0, uint32_t b1) {
    asm volatile(
        "mma.sync.aligned.m16n8k16.row.col.f32.bf16.bf16.f32 "
        "{%0,%1,%2,%3}, {%4,%5,%6,%7}, {%8,%9}, {%0,%1,%2,%3};"
        : "+f"(c0), "+f"(c1), "+f"(c2), "+f"(c3)
        : "r"(a0), "r"(a1), "r"(a2), "r"(a3), "r"(b0), "r"(b1));
}

// ---------------------------------------------------------------------------
__global__ __launch_bounds__(512, 2)
void conv_fused_kernel(const float* __restrict__ x,      // [B,2,H,W]
                       const float* __restrict__ w1,     // [8,2,5,7]
                       const float* __restrict__ b1,     // [8]
                       const float* __restrict__ w2,     // [8,8,3,5]
                       const float* __restrict__ b2)     // [8]
{
    // input tile: [row 22][col 88] bf16x2 word = (ic0, ic1)
    __shared__ uint32_t sInB[IN_ROWS * IN_STR];
    // conv1 out: [18 rows * 80 cols][4 words], word tig = bf16x2 (ic 2tig, 2tig+1)
    __shared__ uint32_t sC1[18 * C1_STR * 4];
    __shared__ uint32_t sW1B[320];   // [(kh*8+kw)*8+oc] = (w1 ic0, ic1) bf16x2
    __shared__ uint32_t sW2B[576];   // [((kh*6+kw)*4+tg)*8+oc]
    __shared__ float sB1s[8], sB2s[8];
    __shared__ float sRed[16 * 8];

    const int tid = threadIdx.x;
    const int wid = tid >> 5;
    const int lid = tid & 31;
    const int g   = lid >> 2;     // fragment group
    const int tig = lid & 3;      // thread in group
    const int bx = blockIdx.x, by = blockIdx.y, b = blockIdx.z;
    const int h0 = by * TH - 3;
    const int w0 = bx * TW - 5;

    // ---- build weight tables ----
    for (int idx = tid; idx < 320; idx += 512) {
        int oc = idx & 7; int t = idx >> 3;
        int kw = t & 7; int kh = t >> 3;
        float lo = 0.f, hi = 0.f;
        if (kw < 7) {
            lo = w1[((oc * 2 + 0) * 5 + kh) * 7 + kw];
            hi = w1[((oc * 2 + 1) * 5 + kh) * 7 + kw];
        }
        sW1B[idx] = bfpack(lo, hi);
    }
    for (int idx = tid; idx < 576; idx += 512) {
        int oc = idx & 7; int t = idx >> 3;
        int tg = t & 3; t >>= 2;
        int kw = t % 6; int kh = t / 6;
        float lo = 0.f, hi = 0.f;
        if (kw < 5) {
            lo = w2[((oc * 8 + 2 * tg)     * 3 + kh) * 5 + kw];
            hi = w2[((oc * 8 + 2 * tg + 1) * 3 + kh) * 5 + kw];
        }
        sW2B[idx] = bfpack(lo, hi);
    }
    if (tid < 8) { sB1s[tid] = b1[tid]; sB2s[tid] = b2[tid]; }

    // ---- load input tile, ic-interleaved bf16 (spikes 0/1 -> exact) ----
    const float* xb = x + (size_t)b * 2 * HH * WW;
    for (int idx = tid; idx < IN_ROWS * IN_STR; idx += 512) {
        int col = idx % IN_STR, row = idx / IN_STR;
        int gh = h0 + row, gw = w0 + col;
        float v0 = 0.f, v1 = 0.f;
        if (gh >= 0 && gh < HH && gw >= 0 && gw < WW) {
            v0 = xb[gh * WW + gw];
            v1 = xb[HH * WW + gh * WW + gw];
        }
        sInB[idx] = bfpack(v0, v1);
    }
    __syncthreads();

    // ---- conv1 via mma: 90 chunks, 2 chunks interleaved per warp ----
    {
        uint32_t bf[10];
        #pragma unroll
        for (int kh = 0; kh < 5; kh++) {
            bf[kh * 2]     = sW1B[(kh * 8 + tig)     * 8 + g];
            bf[kh * 2 + 1] = sW1B[(kh * 8 + tig + 4) * 8 + g];
        }
        const float bi0 = sB1s[2 * tig], bi1 = sB1s[2 * tig + 1];

        #pragma unroll
        for (int base = 0; base < 90; base += 32) {
            const int cc0 = base + wid;
            const int cc1 = cc0 + 16;
            const bool has1 = (cc1 < 90);
            const int r0 = cc0 / 5, c00 = (cc0 % 5) * 16;
            const int r1 = has1 ? (cc1 / 5) : 0;
            const int c01 = has1 ? ((cc1 % 5) * 16) : 0;

            float e0 = bi0, e1 = bi1, e2 = bi0, e3 = bi1;
            float f0 = bi0, f1 = bi1, f2 = bi0, f3 = bi1;
            #pragma unroll
            for (int kh = 0; kh < 5; kh++) {
                const uint32_t* rp0 = &sInB[(r0 + kh) * IN_STR + c00];
                uint32_t a0 = rp0[g + tig];
                uint32_t a1 = rp0[g + 8 + tig];
                uint32_t a2 = rp0[g + tig + 4];
                uint32_t a3 = rp0[g + 8 + tig + 4];
                mma_bf16(e0, e1, e2, e3, a0, a1, a2, a3,
                         bf[kh * 2], bf[kh * 2 + 1]);
                if (has1) {
                    const uint32_t* rp1 = &sInB[(r1 + kh) * IN_STR + c01];
                    uint32_t u0 = rp1[g + tig];
                    uint32_t u1 = rp1[g + 8 + tig];
                    uint32_t u2 = rp1[g + tig + 4];
                    uint32_t u3 = rp1[g + 8 + tig + 4];
                    mma_bf16(f0, f1, f2, f3, u0, u1, u2, u3,
                             bf[kh * 2], bf[kh * 2 + 1]);
                }
            }
            // relu + bf16 pack; C frag (oc pair at m=g,g+8) == conv2 A layout
            sC1[(r0 * C1_STR + c00 + g)     * 4 + tig] = bfpack(fmaxf(e0, 0.f), fmaxf(e1, 0.f));
            sC1[(r0 * C1_STR + c00 + g + 8) * 4 + tig] = bfpack(fmaxf(e2, 0.f), fmaxf(e3, 0.f));
            if (has1) {
                sC1[(r1 * C1_STR + c01 + g)     * 4 + tig] = bfpack(fmaxf(f0, 0.f), fmaxf(f1, 0.f));
                sC1[(r1 * C1_STR + c01 + g + 8) * 4 + tig] = bfpack(fmaxf(f2, 0.f), fmaxf(f3, 0.f));
            }
        }
    }
    __syncthreads();

    // ---- conv2 via mma + pool: warp = out row; 4 chunks interleaved ----
    {
        uint32_t bf[18];
        #pragma unroll
        for (int kh = 0; kh < 3; kh++)
            #pragma unroll
            for (int kw6 = 0; kw6 < 6; kw6++)
                bf[kh * 6 + kw6] = sW2B[((kh * 6 + kw6) * 4 + tig) * 8 + g];
        const float bi0 = sB2s[2 * tig], bi1 = sB2s[2 * tig + 1];
        const int row = wid;

        float d[4][4];
        #pragma unroll
        for (int ch = 0; ch < 4; ch++) {
            d[ch][0] = bi0; d[ch][1] = bi1; d[ch][2] = bi0; d[ch][3] = bi1;
        }
        #pragma unroll
        for (int kh = 0; kh < 3; kh++) {
            #pragma unroll
            for (int j = 0; j < 3; j++) {
                const uint32_t b0 = bf[kh * 6 + 2 * j];
                const uint32_t b1 = bf[kh * 6 + 2 * j + 1];
                #pragma unroll
                for (int ch = 0; ch < 4; ch++) {
                    const uint32_t* pp =
                        &sC1[((row + kh) * C1_STR + ch * 16 + 2 * j) * 4];
                    uint32_t a0 = pp[(g)     * 4 + tig];
                    uint32_t a1 = pp[(g + 8) * 4 + tig];
                    uint32_t a2 = pp[(g + 1) * 4 + tig];
                    uint32_t a3 = pp[(g + 9) * 4 + tig];
                    mma_bf16(d[ch][0], d[ch][1], d[ch][2], d[ch][3],
                             a0, a1, a2, a3, b0, b1);
                }
            }
        }
        float s0 = 0.f, s1 = 0.f;
        #pragma unroll
        for (int ch = 0; ch < 4; ch++) {
            s0 += fmaxf(d[ch][0], 0.f) + fmaxf(d[ch][2], 0.f);
            s1 += fmaxf(d[ch][1], 0.f) + fmaxf(d[ch][3], 0.f);
        }
        // reduce over g (lane bits 2..4); s0 = oc 2tig, s1 = oc 2tig+1
        #pragma unroll
        for (int off = 4; off <= 16; off <<= 1) {
            s0 += __shfl_xor_sync(0xffffffffu, s0, off);
            s1 += __shfl_xor_sync(0xffffffffu, s1, off);
        }
        if (lid < 4) {
            sRed[wid * 8 + 2 * tig]     = s0;
            sRed[wid * 8 + 2 * tig + 1] = s1;
        }
    }
    __syncthreads();

    // deterministic partial write: one fixed slot per block (no atomics)
    if (tid < 8) {
        float t = 0.f;
        #pragma unroll
        for (int wz = 0; wz < 16; wz++) t += sRed[wz * 8 + tid];
        const int ph = by >> 1, sub  = by & 1;
        const int pw = bx / 6,  subx = bx - pw * 6;
        g_partial[(((b * 8 + tid) * 4 + ph) * 4 + pw) * NCONTRIB + sub * 6 + subx] = t;
    }
}

// ---------------------------------------------------------------------------
// Head: grid (24, 32). seg -> branch (seg>>3) and 64-col segment (seg&7).
// 256 thr = 8 ks x 32 jq; jq owns 2 cols. sconv branch == b_proj.
// ---------------------------------------------------------------------------
__global__ __launch_bounds__(256)
void head_kernel(const float* __restrict__ distance,
                 const float* __restrict__ azimuth,
                 const float* __restrict__ elevation,
                 const float* __restrict__ W_dist, const float* __restrict__ b_dist,
                 const float* __restrict__ W_az,   const float* __restrict__ b_az,
                 const float* __restrict__ W_el,   const float* __restrict__ b_el,
                 const float* __restrict__ W_res,  const float* __restrict__ b_res,
                 const float* __restrict__ b_proj,
                 const float* __restrict__ cnn_gain,
                 const float* __restrict__ sconv_gain,
                 float* __restrict__ out)
{
    __shared__ float sv[256];
    __shared__ float sp[128];
    __shared__ float2 sacc[8][32];
    __shared__ float2 slr[8][32];

    const int tid = threadIdx.x;
    const int jq  = tid & 31;
    const int ks  = tid >> 5;          // 0..7
    const int b   = blockIdx.y;
    const int seg = blockIdx.x;        // 0..23
    const int branch = seg >> 3;       // uniform per block
    const int j = (seg & 7) * 64 + jq * 2;   // col within 512

    const float* vec = (branch == 0) ? distance : (branch == 1) ? azimuth : elevation;
    sv[tid] = vec[b * 256 + tid];

    if (branch == 2 && tid < 128) {
        const float* pp = g_partial + (b * 128 + tid) * NCONTRIB;
        float t = 0.f;
        #pragma unroll
        for (int i = 0; i < NCONTRIB; i++) t += pp[i];
        sp[tid] = t * (1.0f / (32.0f * 384.0f));
    }
    __syncthreads();

    const float* Wm = (branch == 0) ? W_dist : (branch == 1) ? W_az : W_el;
    float2 acc = make_float2(0.f, 0.f);
    #pragma unroll 8
    for (int k = ks * 32; k < ks * 32 + 32; k++) {
        float s = sv[k];
        float2 w = *(const float2*)&Wm[k * 512 + j];
        acc.x = fmaf(s, w.x, acc.x);
        acc.y = fmaf(s, w.y, acc.y);
    }
    sacc[ks][jq] = acc;

    if (branch == 2) {
        float2 lr = make_float2(0.f, 0.f);
        #pragma unroll 8
        for (int k = ks * 16; k < ks * 16 + 16; k++) {
            float s = sp[k];
            float2 w = *(const float2*)&W_res[k * 512 + j];
            lr.x = fmaf(s, w.x, lr.x);
            lr.y = fmaf(s, w.y, lr.y);
        }
        slr[ks][jq] = lr;
    }
    __syncthreads();

    if (ks == 0) {
        float rx = 0.f, ry = 0.f;
        #pragma unroll
        for (int p = 0; p < 8; p++) { rx += sacc[p][jq].x; ry += sacc[p][jq].y; }

        float2 r;
        if (branch == 0) {
            r.x = fmaxf(rx + b_dist[j],     0.f);
            r.y = fmaxf(ry + b_dist[j + 1], 0.f);
        } else if (branch == 1) {
            r.x = fmaxf(rx + b_az[j],     0.f);
            r.y = fmaxf(ry + b_az[j + 1], 0.f);
        } else {
            float bx0 = fmaxf(rx + b_el[j],     0.f);
            float by0 = fmaxf(ry + b_el[j + 1], 0.f);
            float lx = 0.f, ly = 0.f;
            #pragma unroll
            for (int p = 0; p < 8; p++) { lx += slr[p][jq].x; ly += slr[p][jq].y; }
            lx += b_res[j]; ly += b_res[j + 1];
            float cs = 0.5f / (1.0f + expf(-cnn_gain[0]));
            float ss = 0.4f / (1.0f + expf(-sconv_gain[0]));
            r.x = fmaxf(bx0 + cs * lx + ss * b_proj[j],     0.f);
            r.y = fmaxf(by0 + cs * ly + ss * b_proj[j + 1], 0.f);
        }
        *(float2*)&out[b * 1536 + branch * 512 + j] = r;
    }
}

// ---------------------------------------------------------------------------
extern "C" void kernel_launch(void* const* d_in, const int* in_sizes, int n_in,
                              void* d_out, int out_size)
{
    const float* distance   = (const float*)d_in[0];
    const float* azimuth    = (const float*)d_in[1];
    const float* elevation  = (const float*)d_in[2];
    const float* rspikes    = (const float*)d_in[3];
    const float* W_dist     = (const float*)d_in[4];
    const float* b_dist     = (const float*)d_in[5];
    const float* W_az       = (const float*)d_in[6];
    const float* b_az       = (const float*)d_in[7];
    const float* W_el       = (const float*)d_in[8];
    const float* b_el       = (const float*)d_in[9];
    const float* conv1_w    = (const float*)d_in[10];
    const float* conv1_b    = (const float*)d_in[11];
    const float* conv2_w    = (const float*)d_in[12];
    const float* conv2_b    = (const float*)d_in[13];
    const float* W_res      = (const float*)d_in[14];
    const float* b_res      = (const float*)d_in[15];
    const float* b_proj     = (const float*)d_in[19];
    const float* cnn_gain   = (const float*)d_in[20];
    const float* sconv_gain = (const float*)d_in[21];

    dim3 gconv(GX, GY, BATCH);
    conv_fused_kernel<<<gconv, 512>>>(rspikes, conv1_w, conv1_b,
                                      conv2_w, conv2_b);

    dim3 ghead(24, BATCH);
    head_kernel<<<ghead, 256>>>(distance, azimuth, elevation,
                                W_dist, b_dist, W_az, b_az, W_el, b_el,
                                W_res, b_res, b_proj, cnn_gain, sconv_gain,
                                (float*)d_out);
}

// round 10
// speedup vs baseline: 1.2625x; 1.2625x over previous
#include <cuda_runtime.h>
#include <math.h>
#include <stdint.h>

// ---------------------------------------------------------------------------
// CombinedElevationEncoder — both convs on bf16 m16n8k16 mma.sync.
//
// Insight 1: dual-CNN branch only consumed through (4,4) block-mean pool ->
//            fuse conv1+relu+conv2+relu+pool; activations never touch GMEM.
// Insight 2: spiking LSTM emits spike(mem-1), mem = sig(o)*tanh(syn) <= 1
//            -> all spikes exactly 0 -> sconv_res == b_proj; scan skipped.
// R8 (3rd submit; prior two rounds died on infra before compile): R5 conv
//     scheduling (best measured) with a 16x128 tile: -10% conv1 chunks/output,
//     -14% input load/output, half the per-block overhead. Dynamic smem
//     (~58KB), 2 CTAs/SM. Head = R7 8-way k-split (11.7us measured).
// ---------------------------------------------------------------------------

#define BATCH 32
#define HH    128
#define WW    1536
#define TH    16
#define TW    128
#define GX    (WW / TW)  // 12
#define GY    (HH / TH)  // 8
#define NCONTRIB 6       // (32/TH)*(384/TW) = 2*3

#define IN_ROWS 22
#define IN_STR  152      // input tile cols (bf16x2 words, ic-interleaved)
#define C1_STR  144      // conv1 plane cols (9 chunks of 16)
#define N_CH1   162      // conv1 chunks: 18 rows * 9

// dynamic smem word offsets
#define OFF_INB 0                          // 22*152 = 3344
#define OFF_C1  3344                       // 18*144*4 = 10368 (16B aligned)
#define OFF_W1B 13712                      // 320
#define OFF_W2B 14032                      // 576
#define OFF_B1  14608
#define OFF_B2  14616
#define OFF_RED 14624                      // 128
#define SMEM_WORDS 14752
#define SMEM_BYTES (SMEM_WORDS * 4)        // 59008

// partial pooled sums: [b][oc][ph][pw][contrib]
__device__ float g_partial[BATCH * 8 * 4 * 4 * NCONTRIB];

// pack two fp32 -> bf16x2 (lo = first arg)
__device__ __forceinline__ uint32_t bfpack(float lo, float hi) {
    uint32_t d;
    asm("cvt.rn.bf16x2.f32 %0, %1, %2;" : "=r"(d) : "f"(hi), "f"(lo));
    return d;
}

// m16n8k16 bf16 mma, accumulate in place (fp32 accum)
__device__ __forceinline__ void mma_bf16(float& c0, float& c1, float& c2, float& c3,
                                         uint32_t a0, uint32_t a1, uint32_t a2, uint32_t a3,
                                         uint32_t b0, uint32_t b1) {
    asm volatile(
        "mma.sync.aligned.m16n8k16.row.col.f32.bf16.bf16.f32 "
        "{%0,%1,%2,%3}, {%4,%5,%6,%7}, {%8,%9}, {%0,%1,%2,%3};"
        : "+f"(c0), "+f"(c1), "+f"(c2), "+f"(c3)
        : "r"(a0), "r"(a1), "r"(a2), "r"(a3), "r"(b0), "r"(b1));
}

// ---------------------------------------------------------------------------
__global__ __launch_bounds__(512, 2)
void conv_fused_kernel(const float* __restrict__ x,      // [B,2,H,W]
                       const float* __restrict__ w1,     // [8,2,5,7]
                       const float* __restrict__ b1,     // [8]
                       const float* __restrict__ w2,     // [8,8,3,5]
                       const float* __restrict__ b2)     // [8]
{
    extern __shared__ __align__(16) uint32_t dsm[];
    uint32_t* sInB = dsm + OFF_INB;   // [row22][col152] bf16x2 (ic0,ic1)
    uint32_t* sC1  = dsm + OFF_C1;    // [pos=row*144+c][4 words: tig -> oc 2tig,2tig+1]
    uint32_t* sW1B = dsm + OFF_W1B;   // [(kh*8+kw)*8+oc]
    uint32_t* sW2B = dsm + OFF_W2B;   // [((kh*6+kw)*4+tg)*8+oc]
    float* sB1s = (float*)(dsm + OFF_B1);
    float* sB2s = (float*)(dsm + OFF_B2);
    float* sRed = (float*)(dsm + OFF_RED);

    const int tid = threadIdx.x;
    const int wid = tid >> 5;
    const int lid = tid & 31;
    const int g   = lid >> 2;     // fragment group
    const int tig = lid & 3;      // thread in group
    const int bx = blockIdx.x, by = blockIdx.y, b = blockIdx.z;
    const int h0 = by * TH - 3;
    const int w0 = bx * TW - 5;

    // ---- build weight tables ----
    for (int idx = tid; idx < 320; idx += 512) {
        int oc = idx & 7; int t = idx >> 3;
        int kw = t & 7; int kh = t >> 3;
        float lo = 0.f, hi = 0.f;
        if (kw < 7) {
            lo = w1[((oc * 2 + 0) * 5 + kh) * 7 + kw];
            hi = w1[((oc * 2 + 1) * 5 + kh) * 7 + kw];
        }
        sW1B[idx] = bfpack(lo, hi);
    }
    for (int idx = tid; idx < 576; idx += 512) {
        int oc = idx & 7; int t = idx >> 3;
        int tg = t & 3; t >>= 2;
        int kw = t % 6; int kh = t / 6;
        float lo = 0.f, hi = 0.f;
        if (kw < 5) {
            lo = w2[((oc * 8 + 2 * tg)     * 3 + kh) * 5 + kw];
            hi = w2[((oc * 8 + 2 * tg + 1) * 3 + kh) * 5 + kw];
        }
        sW2B[idx] = bfpack(lo, hi);
    }
    if (tid < 8) { sB1s[tid] = b1[tid]; sB2s[tid] = b2[tid]; }

    // ---- load input tile, ic-interleaved bf16 (spikes 0/1 -> exact) ----
    const float* xb = x + (size_t)b * 2 * HH * WW;
    for (int idx = tid; idx < IN_ROWS * IN_STR; idx += 512) {
        int col = idx % IN_STR, row = idx / IN_STR;
        int gh = h0 + row, gw = w0 + col;
        float v0 = 0.f, v1 = 0.f;
        if (gh >= 0 && gh < HH && gw >= 0 && gw < WW) {
            v0 = xb[gh * WW + gw];
            v1 = xb[HH * WW + gh * WW + gw];
        }
        sInB[idx] = bfpack(v0, v1);
    }
    __syncthreads();

    // ---- conv1 via mma: 162 chunks (18 rows x 9 col-chunks of 16) ----
    {
        uint32_t bf[10];
        #pragma unroll
        for (int kh = 0; kh < 5; kh++) {
            bf[kh * 2]     = sW1B[(kh * 8 + tig)     * 8 + g];
            bf[kh * 2 + 1] = sW1B[(kh * 8 + tig + 4) * 8 + g];
        }
        const float bi0 = sB1s[2 * tig], bi1 = sB1s[2 * tig + 1];

        for (int cc = wid; cc < N_CH1; cc += 16) {
            const int r  = cc / 9;
            const int c0 = (cc % 9) * 16;
            float d0 = bi0, d1 = bi1, d2 = bi0, d3 = bi1;
            #pragma unroll
            for (int kh = 0; kh < 5; kh++) {
                const uint32_t* rp = &sInB[(r + kh) * IN_STR + c0];
                uint32_t a0 = rp[g + tig];            // m=g,   kw=tig
                uint32_t a1 = rp[g + 8 + tig];        // m=g+8
                uint32_t a2 = rp[g + tig + 4];        // kw=tig+4
                uint32_t a3 = rp[g + 8 + tig + 4];
                mma_bf16(d0, d1, d2, d3, a0, a1, a2, a3,
                         bf[kh * 2], bf[kh * 2 + 1]);
            }
            // relu + bf16 pack; C frag (oc pair at m=g, g+8) == conv2 A layout
            uint32_t lo = bfpack(fmaxf(d0, 0.f), fmaxf(d1, 0.f));
            uint32_t hi = bfpack(fmaxf(d2, 0.f), fmaxf(d3, 0.f));
            sC1[(r * C1_STR + c0 + g)     * 4 + tig] = lo;
            sC1[(r * C1_STR + c0 + g + 8) * 4 + tig] = hi;
        }
    }
    __syncthreads();

    // ---- conv2 via mma + pool partial: warp = out row, 8 col-chunks ----
    {
        uint32_t bf[18];
        #pragma unroll
        for (int kh = 0; kh < 3; kh++)
            #pragma unroll
            for (int kw6 = 0; kw6 < 6; kw6++)
                bf[kh * 6 + kw6] = sW2B[((kh * 6 + kw6) * 4 + tig) * 8 + g];
        const float bi0 = sB2s[2 * tig], bi1 = sB2s[2 * tig + 1];
        const int row = wid;

        float s0 = 0.f, s1 = 0.f;
        #pragma unroll
        for (int ch = 0; ch < 8; ch++) {
            const int c0 = ch * 16;
            float d0 = bi0, d1 = bi1, d2 = bi0, d3 = bi1;
            #pragma unroll
            for (int kh = 0; kh < 3; kh++) {
                #pragma unroll
                for (int j = 0; j < 3; j++) {
                    const int kwb = 2 * j;
                    const uint32_t* pp = &sC1[((row + kh) * C1_STR + c0 + kwb) * 4];
                    uint32_t a0 = pp[(g)     * 4 + tig];   // kw=kwb,   m=g
                    uint32_t a1 = pp[(g + 8) * 4 + tig];   // m=g+8
                    uint32_t a2 = pp[(g + 1) * 4 + tig];   // kw=kwb+1
                    uint32_t a3 = pp[(g + 9) * 4 + tig];
                    mma_bf16(d0, d1, d2, d3, a0, a1, a2, a3,
                             bf[kh * 6 + kwb], bf[kh * 6 + kwb + 1]);
                }
            }
            s0 += fmaxf(d0, 0.f) + fmaxf(d2, 0.f);
            s1 += fmaxf(d1, 0.f) + fmaxf(d3, 0.f);
        }
        // reduce over g (lane bits 2..4); s0 = oc 2tig, s1 = oc 2tig+1
        #pragma unroll
        for (int off = 4; off <= 16; off <<= 1) {
            s0 += __shfl_xor_sync(0xffffffffu, s0, off);
            s1 += __shfl_xor_sync(0xffffffffu, s1, off);
        }
        if (lid < 4) {
            sRed[wid * 8 + 2 * tig]     = s0;
            sRed[wid * 8 + 2 * tig + 1] = s1;
        }
    }
    __syncthreads();

    // deterministic partial write: one fixed slot per block (no atomics)
    if (tid < 8) {
        float t = 0.f;
        #pragma unroll
        for (int wz = 0; wz < 16; wz++) t += sRed[wz * 8 + tid];
        const int ph = by >> 1, sub  = by & 1;      // 2 row-tiles per pool cell
        const int pw = bx / 3,  subx = bx - pw * 3; // 3 col-tiles per pool cell
        g_partial[(((b * 8 + tid) * 4 + ph) * 4 + pw) * NCONTRIB + sub * 3 + subx] = t;
    }
}

// ---------------------------------------------------------------------------
// Head: grid (24, 32). seg -> branch (seg>>3) and 64-col segment (seg&7).
// 256 thr = 8 ks x 32 jq; jq owns 2 cols. sconv branch == b_proj.
// ---------------------------------------------------------------------------
__global__ __launch_bounds__(256)
void head_kernel(const float* __restrict__ distance,
                 const float* __restrict__ azimuth,
                 const float* __restrict__ elevation,
                 const float* __restrict__ W_dist, const float* __restrict__ b_dist,
                 const float* __restrict__ W_az,   const float* __restrict__ b_az,
                 const float* __restrict__ W_el,   const float* __restrict__ b_el,
                 const float* __restrict__ W_res,  const float* __restrict__ b_res,
                 const float* __restrict__ b_proj,
                 const float* __restrict__ cnn_gain,
                 const float* __restrict__ sconv_gain,
                 float* __restrict__ out)
{
    __shared__ float sv[256];
    __shared__ float sp[128];
    __shared__ float2 sacc[8][32];
    __shared__ float2 slr[8][32];

    const int tid = threadIdx.x;
    const int jq  = tid & 31;
    const int ks  = tid >> 5;          // 0..7
    const int b   = blockIdx.y;
    const int seg = blockIdx.x;        // 0..23
    const int branch = seg >> 3;       // uniform per block
    const int j = (seg & 7) * 64 + jq * 2;   // col within 512

    const float* vec = (branch == 0) ? distance : (branch == 1) ? azimuth : elevation;
    sv[tid] = vec[b * 256 + tid];

    if (branch == 2 && tid < 128) {
        const float* pp = g_partial + (b * 128 + tid) * NCONTRIB;
        float t = 0.f;
        #pragma unroll
        for (int i = 0; i < NCONTRIB; i++) t += pp[i];
        sp[tid] = t * (1.0f / (32.0f * 384.0f));
    }
    __syncthreads();

    const float* Wm = (branch == 0) ? W_dist : (branch == 1) ? W_az : W_el;
    float2 acc = make_float2(0.f, 0.f);
    #pragma unroll 8
    for (int k = ks * 32; k < ks * 32 + 32; k++) {
        float s = sv[k];
        float2 w = *(const float2*)&Wm[k * 512 + j];
        acc.x = fmaf(s, w.x, acc.x);
        acc.y = fmaf(s, w.y, acc.y);
    }
    sacc[ks][jq] = acc;

    if (branch == 2) {
        float2 lr = make_float2(0.f, 0.f);
        #pragma unroll 8
        for (int k = ks * 16; k < ks * 16 + 16; k++) {
            float s = sp[k];
            float2 w = *(const float2*)&W_res[k * 512 + j];
            lr.x = fmaf(s, w.x, lr.x);
            lr.y = fmaf(s, w.y, lr.y);
        }
        slr[ks][jq] = lr;
    }
    __syncthreads();

    if (ks == 0) {
        float rx = 0.f, ry = 0.f;
        #pragma unroll
        for (int p = 0; p < 8; p++) { rx += sacc[p][jq].x; ry += sacc[p][jq].y; }

        float2 r;
        if (branch == 0) {
            r.x = fmaxf(rx + b_dist[j],     0.f);
            r.y = fmaxf(ry + b_dist[j + 1], 0.f);
        } else if (branch == 1) {
            r.x = fmaxf(rx + b_az[j],     0.f);
            r.y = fmaxf(ry + b_az[j + 1], 0.f);
        } else {
            float bx0 = fmaxf(rx + b_el[j],     0.f);
            float by0 = fmaxf(ry + b_el[j + 1], 0.f);
            float lx = 0.f, ly = 0.f;
            #pragma unroll
            for (int p = 0; p < 8; p++) { lx += slr[p][jq].x; ly += slr[p][jq].y; }
            lx += b_res[j]; ly += b_res[j + 1];
            float cs = 0.5f / (1.0f + expf(-cnn_gain[0]));
            float ss = 0.4f / (1.0f + expf(-sconv_gain[0]));
            r.x = fmaxf(bx0 + cs * lx + ss * b_proj[j],     0.f);
            r.y = fmaxf(by0 + cs * ly + ss * b_proj[j + 1], 0.f);
        }
        *(float2*)&out[b * 1536 + branch * 512 + j] = r;
    }
}

// ---------------------------------------------------------------------------
extern "C" void kernel_launch(void* const* d_in, const int* in_sizes, int n_in,
                              void* d_out, int out_size)
{
    const float* distance   = (const float*)d_in[0];
    const float* azimuth    = (const float*)d_in[1];
    const float* elevation  = (const float*)d_in[2];
    const float* rspikes    = (const float*)d_in[3];
    const float* W_dist     = (const float*)d_in[4];
    const float* b_dist     = (const float*)d_in[5];
    const float* W_az       = (const float*)d_in[6];
    const float* b_az       = (const float*)d_in[7];
    const float* W_el       = (const float*)d_in[8];
    const float* b_el       = (const float*)d_in[9];
    const float* conv1_w    = (const float*)d_in[10];
    const float* conv1_b    = (const float*)d_in[11];
    const float* conv2_w    = (const float*)d_in[12];
    const float* conv2_b    = (const float*)d_in[13];
    const float* W_res      = (const float*)d_in[14];
    const float* b_res      = (const float*)d_in[15];
    const float* b_proj     = (const float*)d_in[19];
    const float* cnn_gain   = (const float*)d_in[20];
    const float* sconv_gain = (const float*)d_in[21];

    cudaFuncSetAttribute(conv_fused_kernel,
                         cudaFuncAttributeMaxDynamicSharedMemorySize, SMEM_BYTES);

    dim3 gconv(GX, GY, BATCH);
    conv_fused_kernel<<<gconv, 512, SMEM_BYTES>>>(rspikes, conv1_w, conv1_b,
                                                  conv2_w, conv2_b);

    dim3 ghead(24, BATCH);
    head_kernel<<<ghead, 256>>>(distance, azimuth, elevation,
                                W_dist, b_dist, W_az, b_az, W_el, b_el,
                                W_res, b_res, b_proj, cnn_gain, sconv_gain,
                                (float*)d_out);
}

// round 11
// speedup vs baseline: 1.3677x; 1.0833x over previous
#include <cuda_runtime.h>
#include <math.h>
#include <stdint.h>

// ---------------------------------------------------------------------------
// CombinedElevationEncoder — both convs on bf16 m16n8k16 mma.sync.
//
// Insight 1: dual-CNN branch only consumed through (4,4) block-mean pool ->
//            fuse conv1+relu+conv2+relu+pool; activations never touch GMEM.
// Insight 2: spiking LSTM emits spike(mem-1), mem = sig(o)*tanh(syn) <= 1
//            -> all spikes exactly 0 -> sconv_res == b_proj; scan skipped.
// R11: 32x128 tile (halo/fixed-overhead amortization — the validated lever):
//     conv1 row halo 12.5%->6.2%, input load -13%/output, block count 1536,
//     ~105.6KB dynamic smem, 2 CTAs/SM (211KB < 228KB). conv2: each warp
//     serially handles rows wid and wid+16 (keep R5 serial-chain scheduling).
//     Head = R7 8-way k-split (11.7us measured).
// ---------------------------------------------------------------------------

#define BATCH 32
#define HH    128
#define WW    1536
#define TH    32
#define TW    128
#define GX    (WW / TW)  // 12
#define GY    (HH / TH)  // 4
#define NCONTRIB 3       // (32/TH)*(384/TW) = 1*3

#define IN_ROWS 38       // 32 out rows + 2 (conv2) + 4 (conv1) halo
#define IN_STR  152      // input tile cols (bf16x2 words, ic-interleaved)
#define C1_ROWS 34       // conv1 rows needed: out rows -1..+32
#define C1_STR  144      // conv1 plane cols (9 chunks of 16)
#define N_CH1   (C1_ROWS * 9)   // 306 conv1 chunks

// dynamic smem word offsets
#define OFF_INB 0                          // 38*152 = 5776
#define OFF_C1  5776                       // 34*144*4 = 19584 (byte 23104, 16B aligned)
#define OFF_W1B 25360                      // 320
#define OFF_W2B 25680                      // 576
#define OFF_B1  26256
#define OFF_B2  26264
#define OFF_RED 26272                      // 128
#define SMEM_WORDS 26400
#define SMEM_BYTES (SMEM_WORDS * 4)        // 105600

// partial pooled sums: [b][oc][ph][pw][contrib]
__device__ float g_partial[BATCH * 8 * 4 * 4 * NCONTRIB];

// pack two fp32 -> bf16x2 (lo = first arg)
__device__ __forceinline__ uint32_t bfpack(float lo, float hi) {
    uint32_t d;
    asm("cvt.rn.bf16x2.f32 %0, %1, %2;" : "=r"(d) : "f"(hi), "f"(lo));
    return d;
}

// m16n8k16 bf16 mma, accumulate in place (fp32 accum)
__device__ __forceinline__ void mma_bf16(float& c0, float& c1, float& c2, float& c3,
                                         uint32_t a0, uint32_t a1, uint32_t a2, uint32_t a3,
                                         uint32_t b0, uint32_t b1) {
    asm volatile(
        "mma.sync.aligned.m16n8k16.row.col.f32.bf16.bf16.f32 "
        "{%0,%1,%2,%3}, {%4,%5,%6,%7}, {%8,%9}, {%0,%1,%2,%3};"
        : "+f"(c0), "+f"(c1), "+f"(c2), "+f"(c3)
        : "r"(a0), "r"(a1), "r"(a2), "r"(a3), "r"(b0), "r"(b1));
}

// ---------------------------------------------------------------------------
__global__ __launch_bounds__(512, 2)
void conv_fused_kernel(const float* __restrict__ x,      // [B,2,H,W]
                       const float* __restrict__ w1,     // [8,2,5,7]
                       const float* __restrict__ b1,     // [8]
                       const float* __restrict__ w2,     // [8,8,3,5]
                       const float* __restrict__ b2)     // [8]
{
    extern __shared__ __align__(16) uint32_t dsm[];
    uint32_t* sInB = dsm + OFF_INB;   // [row38][col152] bf16x2 (ic0,ic1)
    uint32_t* sC1  = dsm + OFF_C1;    // [pos=row*144+c][4 words: tig -> oc 2tig,2tig+1]
    uint32_t* sW1B = dsm + OFF_W1B;   // [(kh*8+kw)*8+oc]
    uint32_t* sW2B = dsm + OFF_W2B;   // [((kh*6+kw)*4+tg)*8+oc]
    float* sB1s = (float*)(dsm + OFF_B1);
    float* sB2s = (float*)(dsm + OFF_B2);
    float* sRed = (float*)(dsm + OFF_RED);

    const int tid = threadIdx.x;
    const int wid = tid >> 5;
    const int lid = tid & 31;
    const int g   = lid >> 2;     // fragment group
    const int tig = lid & 3;      // thread in group
    const int bx = blockIdx.x, by = blockIdx.y, b = blockIdx.z;
    const int h0 = by * TH - 3;
    const int w0 = bx * TW - 5;

    // ---- build weight tables ----
    for (int idx = tid; idx < 320; idx += 512) {
        int oc = idx & 7; int t = idx >> 3;
        int kw = t & 7; int kh = t >> 3;
        float lo = 0.f, hi = 0.f;
        if (kw < 7) {
            lo = w1[((oc * 2 + 0) * 5 + kh) * 7 + kw];
            hi = w1[((oc * 2 + 1) * 5 + kh) * 7 + kw];
        }
        sW1B[idx] = bfpack(lo, hi);
    }
    for (int idx = tid; idx < 576; idx += 512) {
        int oc = idx & 7; int t = idx >> 3;
        int tg = t & 3; t >>= 2;
        int kw = t % 6; int kh = t / 6;
        float lo = 0.f, hi = 0.f;
        if (kw < 5) {
            lo = w2[((oc * 8 + 2 * tg)     * 3 + kh) * 5 + kw];
            hi = w2[((oc * 8 + 2 * tg + 1) * 3 + kh) * 5 + kw];
        }
        sW2B[idx] = bfpack(lo, hi);
    }
    if (tid < 8) { sB1s[tid] = b1[tid]; sB2s[tid] = b2[tid]; }

    // ---- load input tile, ic-interleaved bf16 (spikes 0/1 -> exact) ----
    const float* xb = x + (size_t)b * 2 * HH * WW;
    for (int idx = tid; idx < IN_ROWS * IN_STR; idx += 512) {
        int col = idx % IN_STR, row = idx / IN_STR;
        int gh = h0 + row, gw = w0 + col;
        float v0 = 0.f, v1 = 0.f;
        if (gh >= 0 && gh < HH && gw >= 0 && gw < WW) {
            v0 = xb[gh * WW + gw];
            v1 = xb[HH * WW + gh * WW + gw];
        }
        sInB[idx] = bfpack(v0, v1);
    }
    __syncthreads();

    // ---- conv1 via mma: 306 chunks (34 rows x 9 col-chunks of 16) ----
    {
        uint32_t bf[10];
        #pragma unroll
        for (int kh = 0; kh < 5; kh++) {
            bf[kh * 2]     = sW1B[(kh * 8 + tig)     * 8 + g];
            bf[kh * 2 + 1] = sW1B[(kh * 8 + tig + 4) * 8 + g];
        }
        const float bi0 = sB1s[2 * tig], bi1 = sB1s[2 * tig + 1];

        for (int cc = wid; cc < N_CH1; cc += 16) {
            const int r  = cc / 9;
            const int c0 = (cc % 9) * 16;
            float d0 = bi0, d1 = bi1, d2 = bi0, d3 = bi1;
            #pragma unroll
            for (int kh = 0; kh < 5; kh++) {
                const uint32_t* rp = &sInB[(r + kh) * IN_STR + c0];
                uint32_t a0 = rp[g + tig];            // m=g,   kw=tig
                uint32_t a1 = rp[g + 8 + tig];        // m=g+8
                uint32_t a2 = rp[g + tig + 4];        // kw=tig+4
                uint32_t a3 = rp[g + 8 + tig + 4];
                mma_bf16(d0, d1, d2, d3, a0, a1, a2, a3,
                         bf[kh * 2], bf[kh * 2 + 1]);
            }
            // relu + bf16 pack; C frag (oc pair at m=g, g+8) == conv2 A layout
            uint32_t lo = bfpack(fmaxf(d0, 0.f), fmaxf(d1, 0.f));
            uint32_t hi = bfpack(fmaxf(d2, 0.f), fmaxf(d3, 0.f));
            sC1[(r * C1_STR + c0 + g)     * 4 + tig] = lo;
            sC1[(r * C1_STR + c0 + g + 8) * 4 + tig] = hi;
        }
    }
    __syncthreads();

    // ---- conv2 via mma + pool partial: warp = rows wid, wid+16; 8 chunks ----
    {
        uint32_t bf[18];
        #pragma unroll
        for (int kh = 0; kh < 3; kh++)
            #pragma unroll
            for (int kw6 = 0; kw6 < 6; kw6++)
                bf[kh * 6 + kw6] = sW2B[((kh * 6 + kw6) * 4 + tig) * 8 + g];
        const float bi0 = sB2s[2 * tig], bi1 = sB2s[2 * tig + 1];

        float s0 = 0.f, s1 = 0.f;
        #pragma unroll
        for (int rr = 0; rr < 2; rr++) {
            const int row = wid + rr * 16;      // out rows 0..31
            #pragma unroll
            for (int ch = 0; ch < 8; ch++) {
                const int c0 = ch * 16;
                float d0 = bi0, d1 = bi1, d2 = bi0, d3 = bi1;
                #pragma unroll
                for (int kh = 0; kh < 3; kh++) {
                    #pragma unroll
                    for (int j = 0; j < 3; j++) {
                        const int kwb = 2 * j;
                        const uint32_t* pp = &sC1[((row + kh) * C1_STR + c0 + kwb) * 4];
                        uint32_t a0 = pp[(g)     * 4 + tig];   // kw=kwb,   m=g
                        uint32_t a1 = pp[(g + 8) * 4 + tig];   // m=g+8
                        uint32_t a2 = pp[(g + 1) * 4 + tig];   // kw=kwb+1
                        uint32_t a3 = pp[(g + 9) * 4 + tig];
                        mma_bf16(d0, d1, d2, d3, a0, a1, a2, a3,
                                 bf[kh * 6 + kwb], bf[kh * 6 + kwb + 1]);
                    }
                }
                s0 += fmaxf(d0, 0.f) + fmaxf(d2, 0.f);
                s1 += fmaxf(d1, 0.f) + fmaxf(d3, 0.f);
            }
        }
        // reduce over g (lane bits 2..4); s0 = oc 2tig, s1 = oc 2tig+1
        #pragma unroll
        for (int off = 4; off <= 16; off <<= 1) {
            s0 += __shfl_xor_sync(0xffffffffu, s0, off);
            s1 += __shfl_xor_sync(0xffffffffu, s1, off);
        }
        if (lid < 4) {
            sRed[wid * 8 + 2 * tig]     = s0;
            sRed[wid * 8 + 2 * tig + 1] = s1;
        }
    }
    __syncthreads();

    // deterministic partial write: one fixed slot per block (no atomics)
    if (tid < 8) {
        float t = 0.f;
        #pragma unroll
        for (int wz = 0; wz < 16; wz++) t += sRed[wz * 8 + tid];
        const int ph = by;                          // 1 row-tile per pool cell
        const int pw = bx / 3,  subx = bx - pw * 3; // 3 col-tiles per pool cell
        g_partial[(((b * 8 + tid) * 4 + ph) * 4 + pw) * NCONTRIB + subx] = t;
    }
}

// ---------------------------------------------------------------------------
// Head: grid (24, 32). seg -> branch (seg>>3) and 64-col segment (seg&7).
// 256 thr = 8 ks x 32 jq; jq owns 2 cols. sconv branch == b_proj.
// ---------------------------------------------------------------------------
__global__ __launch_bounds__(256)
void head_kernel(const float* __restrict__ distance,
                 const float* __restrict__ azimuth,
                 const float* __restrict__ elevation,
                 const float* __restrict__ W_dist, const float* __restrict__ b_dist,
                 const float* __restrict__ W_az,   const float* __restrict__ b_az,
                 const float* __restrict__ W_el,   const float* __restrict__ b_el,
                 const float* __restrict__ W_res,  const float* __restrict__ b_res,
                 const float* __restrict__ b_proj,
                 const float* __restrict__ cnn_gain,
                 const float* __restrict__ sconv_gain,
                 float* __restrict__ out)
{
    __shared__ float sv[256];
    __shared__ float sp[128];
    __shared__ float2 sacc[8][32];
    __shared__ float2 slr[8][32];

    const int tid = threadIdx.x;
    const int jq  = tid & 31;
    const int ks  = tid >> 5;          // 0..7
    const int b   = blockIdx.y;
    const int seg = blockIdx.x;        // 0..23
    const int branch = seg >> 3;       // uniform per block
    const int j = (seg & 7) * 64 + jq * 2;   // col within 512

    const float* vec = (branch == 0) ? distance : (branch == 1) ? azimuth : elevation;
    sv[tid] = vec[b * 256 + tid];

    if (branch == 2 && tid < 128) {
        const float* pp = g_partial + (b * 128 + tid) * NCONTRIB;
        float t = 0.f;
        #pragma unroll
        for (int i = 0; i < NCONTRIB; i++) t += pp[i];
        sp[tid] = t * (1.0f / (32.0f * 384.0f));
    }
    __syncthreads();

    const float* Wm = (branch == 0) ? W_dist : (branch == 1) ? W_az : W_el;
    float2 acc = make_float2(0.f, 0.f);
    #pragma unroll 8
    for (int k = ks * 32; k < ks * 32 + 32; k++) {
        float s = sv[k];
        float2 w = *(const float2*)&Wm[k * 512 + j];
        acc.x = fmaf(s, w.x, acc.x);
        acc.y = fmaf(s, w.y, acc.y);
    }
    sacc[ks][jq] = acc;

    if (branch == 2) {
        float2 lr = make_float2(0.f, 0.f);
        #pragma unroll 8
        for (int k = ks * 16; k < ks * 16 + 16; k++) {
            float s = sp[k];
            float2 w = *(const float2*)&W_res[k * 512 + j];
            lr.x = fmaf(s, w.x, lr.x);
            lr.y = fmaf(s, w.y, lr.y);
        }
        slr[ks][jq] = lr;
    }
    __syncthreads();

    if (ks == 0) {
        float rx = 0.f, ry = 0.f;
        #pragma unroll
        for (int p = 0; p < 8; p++) { rx += sacc[p][jq].x; ry += sacc[p][jq].y; }

        float2 r;
        if (branch == 0) {
            r.x = fmaxf(rx + b_dist[j],     0.f);
            r.y = fmaxf(ry + b_dist[j + 1], 0.f);
        } else if (branch == 1) {
            r.x = fmaxf(rx + b_az[j],     0.f);
            r.y = fmaxf(ry + b_az[j + 1], 0.f);
        } else {
            float bx0 = fmaxf(rx + b_el[j],     0.f);
            float by0 = fmaxf(ry + b_el[j + 1], 0.f);
            float lx = 0.f, ly = 0.f;
            #pragma unroll
            for (int p = 0; p < 8; p++) { lx += slr[p][jq].x; ly += slr[p][jq].y; }
            lx += b_res[j]; ly += b_res[j + 1];
            float cs = 0.5f / (1.0f + expf(-cnn_gain[0]));
            float ss = 0.4f / (1.0f + expf(-sconv_gain[0]));
            r.x = fmaxf(bx0 + cs * lx + ss * b_proj[j],     0.f);
            r.y = fmaxf(by0 + cs * ly + ss * b_proj[j + 1], 0.f);
        }
        *(float2*)&out[b * 1536 + branch * 512 + j] = r;
    }
}

// ---------------------------------------------------------------------------
extern "C" void kernel_launch(void* const* d_in, const int* in_sizes, int n_in,
                              void* d_out, int out_size)
{
    const float* distance   = (const float*)d_in[0];
    const float* azimuth    = (const float*)d_in[1];
    const float* elevation  = (const float*)d_in[2];
    const float* rspikes    = (const float*)d_in[3];
    const float* W_dist     = (const float*)d_in[4];
    const float* b_dist     = (const float*)d_in[5];
    const float* W_az       = (const float*)d_in[6];
    const float* b_az       = (const float*)d_in[7];
    const float* W_el       = (const float*)d_in[8];
    const float* b_el       = (const float*)d_in[9];
    const float* conv1_w    = (const float*)d_in[10];
    const float* conv1_b    = (const float*)d_in[11];
    const float* conv2_w    = (const float*)d_in[12];
    const float* conv2_b    = (const float*)d_in[13];
    const float* W_res      = (const float*)d_in[14];
    const float* b_res      = (const float*)d_in[15];
    const float* b_proj     = (const float*)d_in[19];
    const float* cnn_gain   = (const float*)d_in[20];
    const float* sconv_gain = (const float*)d_in[21];

    cudaFuncSetAttribute(conv_fused_kernel,
                         cudaFuncAttributeMaxDynamicSharedMemorySize, SMEM_BYTES);

    dim3 gconv(GX, GY, BATCH);
    conv_fused_kernel<<<gconv, 512, SMEM_BYTES>>>(rspikes, conv1_w, conv1_b,
                                                  conv2_w, conv2_b);

    dim3 ghead(24, BATCH);
    head_kernel<<<ghead, 256>>>(distance, azimuth, elevation,
                                W_dist, b_dist, W_az, b_az, W_el, b_el,
                                W_res, b_res, b_proj, cnn_gain, sconv_gain,
                                (float*)d_out);
}